// round 7
// baseline (speedup 1.0000x reference)
#include <cuda_runtime.h>

#define D      3072
#define BATCH  512
#define NC     100
#define RS     48      // row splits for column-sum kernel
#define RROWS  64      // rows per split (48*64 = 3072)
#define BK     96      // GEMM k-tile per CTA
#define KC     32      // k-chunk staged in smem
#define NSPLIT 32      // D / BK
#define BM     64      // GEMM m-tile
#define MT     8       // BATCH / BM
#define ZSTR   33      // Zs row stride (conflict-free)
#define WTS    104     // Wt row stride in floats (16B-aligned rows)
#define OSTR   101     // epilogue staging stride

// ---- device scratch (static, no allocation) ----
__device__ float g_pA[RS * D];
__device__ float g_pB[RS * D];
__device__ float g_fcrow[NC];
__device__ float g_part1;
__device__ float g_scratch[NSPLIT * BATCH * NC];   // 6.55 MB
__device__ unsigned g_cnt[MT];

// ---- f32x2 packed-FMA helpers (sm_103a FFMA2) ----
__device__ __forceinline__ unsigned long long pk2(float lo, float hi) {
    unsigned long long r;
    asm("mov.b64 %0, {%1, %2};" : "=l"(r) : "f"(lo), "f"(hi));
    return r;
}
__device__ __forceinline__ void fma2(unsigned long long& d,
                                     unsigned long long a,
                                     unsigned long long b) {
    asm("fma.rn.f32x2 %0, %1, %2, %0;" : "+l"(d) : "l"(a), "l"(b));
}
__device__ __forceinline__ float2 up2(unsigned long long v) {
    float2 f;
    asm("mov.b64 {%0, %1}, %2;" : "=f"(f.x), "=f"(f.y) : "l"(v));
    return f;
}

// ---- FMA-pipe sincos (validated: rel_err 4.5e-7 in R5) ----
__device__ __forceinline__ void fast_sincos(float x, float& sn, float& cs) {
    const float BIGMAGIC = 12582912.0f;               // 1.5 * 2^23
    float y = fmaf(x, 0.63661977236758134f, BIGMAGIC);
    unsigned q = __float_as_uint(y);
    float n = y - BIGMAGIC;
    float r = fmaf(n, -1.57079637050628662109375f, x);
    r = fmaf(n, 4.37113900018624283e-8f, r);
    float r2 = r * r;
    float ps = fmaf(r2, -1.9515295891e-4f, 8.3321608736e-3f);
    ps = fmaf(r2, ps, -1.6666654611e-1f);
    float sinp = fmaf(r * r2, ps, r);
    float pc = fmaf(r2, 2.443315711809948e-5f, -1.388731625493765e-3f);
    pc = fmaf(r2, pc, 4.166664568298827e-2f);
    pc = fmaf(r2, pc, -0.5f);
    float cosp = fmaf(r2, pc, 1.0f);
    bool swap = (q & 1u);
    float us = swap ? cosp : sinp;
    float uc = swap ? sinp : cosp;
    sn = __uint_as_float(__float_as_uint(us) ^ ((q & 2u) << 30));
    cs = __uint_as_float(__float_as_uint(uc) ^ (((q + 1u) & 2u) << 30));
}

// ============================================================
// K1: z in {0,1}: partial column sums of a/b (HBM-bound, float4).
//     z == 2   : fcrow row-sums + part1 + counter reset (overlapped).
// grid (3, 48, 3), block 256.
// ============================================================
__global__ void k1_prep(const float4* __restrict__ a,
                        const float4* __restrict__ b,
                        const float* __restrict__ fc_w,
                        const float* __restrict__ w,
                        const float* __restrict__ n_param) {
    if (blockIdx.z < 2) {
        int d4 = blockIdx.x * 256 + threadIdx.x;       // 0..767
        int rs = blockIdx.y;
        const float4* src = (blockIdx.z == 0) ? a : b;
        float*        dst = (blockIdx.z == 0) ? g_pA : g_pB;
        const float4* p = src + rs * RROWS * (D / 4) + d4;
        float4 acc = make_float4(0.f, 0.f, 0.f, 0.f);
#pragma unroll 8
        for (int r = 0; r < RROWS; r++) {
            float4 v = p[r * (D / 4)];
            acc.x += v.x; acc.y += v.y; acc.z += v.z; acc.w += v.w;
        }
        *reinterpret_cast<float4*>(dst + rs * D + d4 * 4) = acc;
        return;
    }
    // ---- misc blocks ----
    int flat = blockIdx.y * 3 + blockIdx.x;            // 0..143
    int t = threadIdx.x, wid = t >> 5, lane = t & 31;
    if (flat < 13) {                                   // fcrow: 13 blocks x 8 warps
        int c = flat * 8 + wid;
        if (c < NC) {
            float s = 0.f;
            for (int j = lane; j < D; j += 32) s += fc_w[c * D + j];
#pragma unroll
            for (int o = 16; o; o >>= 1) s += __shfl_xor_sync(0xffffffffu, s, o);
            if (lane == 0) g_fcrow[c] = s;
        }
    } else if (flat == 13) {
        if (t == 0) {
            float p1 = 0.f;
#pragma unroll
            for (int i = 0; i < 4; i++)
                p1 += w[i + 1] * n_param[i + 1] + w[i] * n_param[i];
            g_part1 = p1;
        }
        if (t < MT) g_cnt[t] = 0u;                     // reset spin counters
    }
}

// ============================================================
// K3: fused everything else.
//  1. prologue: reduce colA/colB slice for this CTA's k-range (from g_pA/g_pB)
//  2. mainloop: Z on-the-fly (poly sincos) + FFMA2 GEMM, 3 chunks of KC=32
//  3. epilogue: stage tile -> coalesced scratch stores
//  4. spin on per-mtile counter; all 32 split-CTAs then reduce disjoint
//     200-output regions in FIXED split order (deterministic) + bias.
// grid (8, 32) = 256 CTAs, block 160 (5 warps), occ 4 (all resident).
// ============================================================
__global__ __launch_bounds__(160, 4)
void k3_fused(const float* __restrict__ xf, const float* __restrict__ fc_w,
              const float* __restrict__ fc_b, float* __restrict__ out) {
    __shared__ float colAs[BK], colBs[BK];
    __shared__ float sm[BM * OSTR];                    // 6464 floats = 25.9KB
    float* Zs = sm;                                    // [64][33] = 2112
    float* Wt = sm + BM * ZSTR;                        // [32][104] = 3328 (16B-aligned)

    const int t     = threadIdx.x;
    const int lane  = t & 31;
    const int wrp   = t >> 5;                          // 0..4 -> 20-col group
    const int mtile = blockIdx.x;                      // 0..7
    const int split = blockIdx.y;                      // 0..31
    const int k0    = split * BK;

    // ---- 1. per-CTA colsum finalize for cols [k0, k0+96) ----
    for (int c = t; c < BK; c += 160) {
        float sa = 0.f, sb = 0.f;
#pragma unroll 8
        for (int s = 0; s < RS; s++) {
            sa += g_pA[s * D + k0 + c];
            sb += g_pB[s * D + k0 + c];
        }
        colAs[c] = sa;
        colBs[c] = sb;
    }
    __syncthreads();

    unsigned long long acc[2][10];
#pragma unroll
    for (int m = 0; m < 2; m++)
#pragma unroll
        for (int n = 0; n < 10; n++) acc[m][n] = 0ull;

    // ---- 2. mainloop over 3 chunks of KC=32 ----
    for (int chunk = 0; chunk < BK / KC; chunk++) {
        const int kc = chunk * KC;         // local
        const int gk = k0 + kc;            // global

        // Z chunk: 64 rows x 8 quads
        for (int i = t; i < BM * (KC / 4); i += 160) {
            int row = i >> 3;
            int kq  = i & 7;
            float4 v = *reinterpret_cast<const float4*>(
                xf + (mtile * BM + row) * D + gk + kq * 4);
            float vv[4] = {v.x, v.y, v.z, v.w};
#pragma unroll
            for (int j = 0; j < 4; j++) {
                int kk = kq * 4 + j;
                float sn, cs;
                fast_sincos(vv[j], sn, cs);
                Zs[row * ZSTR + kk] = cs * colAs[kc + kk] + sn * colBs[kc + kk];
            }
        }
        // W chunk: 100 rows x 8 quads, transposed into Wt[k][c]
        for (int i = t; i < NC * (KC / 4); i += 160) {
            int c  = i >> 3;
            int kq = i & 7;
            float4 v = *reinterpret_cast<const float4*>(fc_w + c * D + gk + kq * 4);
            Wt[(kq * 4 + 0) * WTS + c] = v.x;
            Wt[(kq * 4 + 1) * WTS + c] = v.y;
            Wt[(kq * 4 + 2) * WTS + c] = v.z;
            Wt[(kq * 4 + 3) * WTS + c] = v.w;
        }
        __syncthreads();

#pragma unroll 4
        for (int k = 0; k < KC; k++) {
            // 5 LDS.128 broadcast loads -> 10 packed w pairs
            unsigned long long wv[10];
            const float4* wp = reinterpret_cast<const float4*>(
                &Wt[k * WTS + wrp * 20]);
#pragma unroll
            for (int q = 0; q < 5; q++) {
                float4 v = wp[q];
                wv[2 * q]     = pk2(v.x, v.y);
                wv[2 * q + 1] = pk2(v.z, v.w);
            }
            float z0 = Zs[lane * ZSTR + k];
            float z1 = Zs[(lane + 32) * ZSTR + k];
            unsigned long long zz0 = pk2(z0, z0);
            unsigned long long zz1 = pk2(z1, z1);
#pragma unroll
            for (int n = 0; n < 10; n++) fma2(acc[0][n], zz0, wv[n]);
#pragma unroll
            for (int n = 0; n < 10; n++) fma2(acc[1][n], zz1, wv[n]);
        }
        __syncthreads();
    }

    // ---- 3. epilogue: stage -> coalesced scratch stores ----
#pragma unroll
    for (int m = 0; m < 2; m++) {
        int r = lane + 32 * m;
#pragma unroll
        for (int n = 0; n < 10; n++) {
            float2 v = up2(acc[m][n]);
            sm[r * OSTR + wrp * 20 + 2 * n]     = v.x;
            sm[r * OSTR + wrp * 20 + 2 * n + 1] = v.y;
        }
    }
    __syncthreads();
    {
        float* dst = g_scratch + split * (BATCH * NC) + mtile * (BM * NC);
        for (int i = t; i < BM * NC; i += 160) {
            int row = i / NC;
            int c   = i - row * NC;
            dst[i] = sm[row * OSTR + c];
        }
    }

    // ---- 4. deterministic cross-CTA reduction ----
    __threadfence();            // make scratch stores visible (release)
    __syncthreads();
    if (t == 0) {
        atomicAdd(&g_cnt[mtile], 1u);
        while (atomicAdd(&g_cnt[mtile], 0u) < (unsigned)NSPLIT)
            __nanosleep(64);
    }
    __syncthreads();
    __threadfence();            // acquire

    // this CTA reduces outputs [split*200, split*200+200) of its mtile,
    // summing splits in fixed order 0..31 (bitwise deterministic).
    const int rbase = split * 200;
    for (int j = t; j < 200; j += 160) {
        const int fo = mtile * (BM * NC) + rbase + j;   // flat out index
        float a0 = 0.f, a1 = 0.f, a2 = 0.f, a3 = 0.f;
#pragma unroll
        for (int s = 0; s < NSPLIT; s += 8) {
            float v[8];
#pragma unroll
            for (int u = 0; u < 8; u++)
                v[u] = __ldcg(&g_scratch[(s + u) * (BATCH * NC) + fo]);
            a0 += v[0] + v[4];
            a1 += v[1] + v[5];
            a2 += v[2] + v[6];
            a3 += v[3] + v[7];
        }
        int c = fo % NC;
        out[fo] = (a0 + a1) + (a2 + a3) + g_part1 * g_fcrow[c] + fc_b[c];
    }
}

// ============================================================
extern "C" void kernel_launch(void* const* d_in, const int* in_sizes, int n_in,
                              void* d_out, int out_size) {
    const float* x       = (const float*)d_in[0];   // [512,3072]
    const float* a       = (const float*)d_in[1];   // [3072,3072,1]
    const float* b       = (const float*)d_in[2];   // [3072,3072,1]
    const float* w       = (const float*)d_in[3];   // [5]
    const float* n_param = (const float*)d_in[4];   // [5]
    const float* fc_w    = (const float*)d_in[5];   // [100,3072]
    const float* fc_b    = (const float*)d_in[6];   // [100]
    float* out = (float*)d_out;                     // [512,100]

    k1_prep<<<dim3(3, RS, 3), 256>>>((const float4*)a, (const float4*)b,
                                     fc_w, w, n_param);
    k3_fused<<<dim3(MT, NSPLIT), 160>>>(x, fc_w, fc_b, out);
}

// round 10
// speedup vs baseline: 1.0016x; 1.0016x over previous
#include <cuda_runtime.h>

#define D      3072
#define BATCH  512
#define NC     100
#define RS     48      // row splits for column-sum kernel
#define RROWS  64      // rows per split (48*64 = 3072)
#define BK     48      // GEMM k-tile per CTA (single smem stage)
#define NSPLIT 64      // D / BK
#define BM     64      // GEMM m-tile
#define MT     8       // BATCH / BM
#define ZSTR   49      // Zs row stride (>= BK=48; 49 mod 32 = 17 odd -> conflict-free)
#define WTS    104     // Wt row stride (floats), 16B-aligned rows
#define OSTR   101     // epilogue staging stride

// ---- device scratch (static, no allocation) ----
__device__ float g_pA[RS * D];
__device__ float g_pB[RS * D];
__device__ float g_fcrow[NC];
__device__ float g_part1;
__device__ float g_scratch[NSPLIT * BATCH * NC];   // 13.1 MB
__device__ unsigned g_cnt[MT];

// ---- f32x2 packed-FMA helpers (sm_103a FFMA2) ----
__device__ __forceinline__ unsigned long long pk2(float lo, float hi) {
    unsigned long long r;
    asm("mov.b64 %0, {%1, %2};" : "=l"(r) : "f"(lo), "f"(hi));
    return r;
}
__device__ __forceinline__ void fma2(unsigned long long& d,
                                     unsigned long long a,
                                     unsigned long long b) {
    asm("fma.rn.f32x2 %0, %1, %2, %0;" : "+l"(d) : "l"(a), "l"(b));
}
__device__ __forceinline__ float2 up2(unsigned long long v) {
    float2 f;
    asm("mov.b64 {%0, %1}, %2;" : "=f"(f.x), "=f"(f.y) : "l"(v));
    return f;
}

// ---- FMA-pipe sincos (validated rel_err ~4.5e-7) ----
__device__ __forceinline__ void fast_sincos(float x, float& sn, float& cs) {
    const float BIGMAGIC = 12582912.0f;               // 1.5 * 2^23
    float y = fmaf(x, 0.63661977236758134f, BIGMAGIC);
    unsigned q = __float_as_uint(y);
    float n = y - BIGMAGIC;
    float r = fmaf(n, -1.57079637050628662109375f, x);
    r = fmaf(n, 4.37113900018624283e-8f, r);
    float r2 = r * r;
    float ps = fmaf(r2, -1.9515295891e-4f, 8.3321608736e-3f);
    ps = fmaf(r2, ps, -1.6666654611e-1f);
    float sinp = fmaf(r * r2, ps, r);
    float pc = fmaf(r2, 2.443315711809948e-5f, -1.388731625493765e-3f);
    pc = fmaf(r2, pc, 4.166664568298827e-2f);
    pc = fmaf(r2, pc, -0.5f);
    float cosp = fmaf(r2, pc, 1.0f);
    bool swap = (q & 1u);
    float us = swap ? cosp : sinp;
    float uc = swap ? sinp : cosp;
    sn = __uint_as_float(__float_as_uint(us) ^ ((q & 2u) << 30));
    cs = __uint_as_float(__float_as_uint(uc) ^ (((q + 1u) & 2u) << 30));
}

// ============================================================
// K1: z in {0,1}: partial column sums of a/b (HBM-bound, float4).
//     z == 2   : fcrow row-sums + part1 + counter reset (overlapped).
// grid (3, 48, 3), block 256.
// ============================================================
__global__ void k1_prep(const float4* __restrict__ a,
                        const float4* __restrict__ b,
                        const float* __restrict__ fc_w,
                        const float* __restrict__ w,
                        const float* __restrict__ n_param) {
    if (blockIdx.z < 2) {
        int d4 = blockIdx.x * 256 + threadIdx.x;       // 0..767
        int rs = blockIdx.y;
        const float4* src = (blockIdx.z == 0) ? a : b;
        float*        dst = (blockIdx.z == 0) ? g_pA : g_pB;
        const float4* p = src + rs * RROWS * (D / 4) + d4;
        float4 acc = make_float4(0.f, 0.f, 0.f, 0.f);
#pragma unroll 8
        for (int r = 0; r < RROWS; r++) {
            float4 v = p[r * (D / 4)];
            acc.x += v.x; acc.y += v.y; acc.z += v.z; acc.w += v.w;
        }
        *reinterpret_cast<float4*>(dst + rs * D + d4 * 4) = acc;
        return;
    }
    int flat = blockIdx.y * 3 + blockIdx.x;            // 0..143
    int t = threadIdx.x, wid = t >> 5, lane = t & 31;
    if (flat < 13) {                                   // fcrow: 13 blocks x 8 warps
        int c = flat * 8 + wid;
        if (c < NC) {
            float s = 0.f;
            for (int j = lane; j < D; j += 32) s += fc_w[c * D + j];
#pragma unroll
            for (int o = 16; o; o >>= 1) s += __shfl_xor_sync(0xffffffffu, s, o);
            if (lane == 0) g_fcrow[c] = s;
        }
    } else if (flat == 13) {
        if (t == 0) {
            float p1 = 0.f;
#pragma unroll
            for (int i = 0; i < 4; i++)
                p1 += w[i + 1] * n_param[i + 1] + w[i] * n_param[i];
            g_part1 = p1;
        }
        if (t < MT) g_cnt[t] = 0u;                     // reset spin counters
    }
}

// ============================================================
// K3: fused Z-build + FFMA2 GEMM + deterministic cross-CTA reduce.
// grid (8, 64) = 512 CTAs (single wave at occ 4), block 160 (5 warps).
// Warp w covers cols [w*20, w*20+20) as 10 natural (c, c+1) pairs read
// straight from smem via ulonglong2 (LDS.128 broadcast, zero movs).
// Thread tile = 2 rows x 20 cols.
// ============================================================
__global__ __launch_bounds__(160, 4)
void k3_fused(const float* __restrict__ xf, const float* __restrict__ fc_w,
              const float* __restrict__ fc_b, float* __restrict__ out) {
    __shared__ float colAs[BK], colBs[BK];
    __shared__ float sm[BM * ZSTR + BK * WTS];  // 3136 + 4992 = 8128 f = 32.5KB
    float* Zs = sm;                             // [64][49]
    float* Wt = sm + BM * ZSTR;                 // [48][104], cols contiguous

    const int t     = threadIdx.x;
    const int lane  = t & 31;
    const int wrp   = t >> 5;                   // 0..4
    const int mtile = blockIdx.x;               // 0..7
    const int split = blockIdx.y;               // 0..63
    const int k0    = split * BK;

    // ---- prologue: per-CTA colsum finalize for cols [k0, k0+48) ----
    if (t < 96) {
        int c = (t >= 48) ? t - 48 : t;
        const float* src = (t < 48) ? g_pA : g_pB;
        float*       dst = (t < 48) ? colAs : colBs;
        float s = 0.f;
#pragma unroll 8
        for (int r = 0; r < RS; r++) s += src[r * D + k0 + c];
        dst[c] = s;
    }
    __syncthreads();

    // ---- Z tile: 64 rows x 12 quads (poly sincos, FMA pipe) ----
    for (int i = t; i < BM * (BK / 4); i += 160) {
        int row = i / 12;
        int kq  = i - row * 12;
        float4 v = *reinterpret_cast<const float4*>(
            xf + (mtile * BM + row) * D + k0 + kq * 4);
        float vv[4] = {v.x, v.y, v.z, v.w};
#pragma unroll
        for (int j = 0; j < 4; j++) {
            int kk = kq * 4 + j;
            float sn, cs;
            fast_sincos(vv[j], sn, cs);
            Zs[row * ZSTR + kk] = cs * colAs[kk] + sn * colBs[kk];
        }
    }
    // ---- W tile: 100 rows x 12 quads, transposed into Wt[k][c] ----
    for (int i = t; i < NC * (BK / 4); i += 160) {
        int c  = i / 12;
        int kq = i - c * 12;
        float4 v = *reinterpret_cast<const float4*>(fc_w + c * D + k0 + kq * 4);
        Wt[(kq * 4 + 0) * WTS + c] = v.x;
        Wt[(kq * 4 + 1) * WTS + c] = v.y;
        Wt[(kq * 4 + 2) * WTS + c] = v.z;
        Wt[(kq * 4 + 3) * WTS + c] = v.w;
    }
    __syncthreads();

    // ---- mainloop: K=48, 2 rows x 20 cols per thread ----
    unsigned long long acc[2][10];
#pragma unroll
    for (int m = 0; m < 2; m++)
#pragma unroll
        for (int n = 0; n < 10; n++) acc[m][n] = 0ull;

#pragma unroll 3
    for (int k = 0; k < BK; k++) {
        // 5x LDS.128 (warp-uniform broadcast) -> 10 natural (c,c+1) pairs
        const ulonglong2* wp = reinterpret_cast<const ulonglong2*>(
            &Wt[k * WTS + wrp * 20]);
        unsigned long long wv[10];
#pragma unroll
        for (int q = 0; q < 5; q++) {
            ulonglong2 u = wp[q];
            wv[2 * q]     = u.x;      // floats (4q, 4q+1)
            wv[2 * q + 1] = u.y;      // floats (4q+2, 4q+3)
        }
        float z0 = Zs[lane * ZSTR + k];
        float z1 = Zs[(lane + 32) * ZSTR + k];
        unsigned long long zz0 = pk2(z0, z0);
        unsigned long long zz1 = pk2(z1, z1);
#pragma unroll
        for (int n = 0; n < 10; n++) fma2(acc[0][n], zz0, wv[n]);
#pragma unroll
        for (int n = 0; n < 10; n++) fma2(acc[1][n], zz1, wv[n]);
    }
    __syncthreads();

    // ---- epilogue: stage tile -> coalesced scratch stores ----
#pragma unroll
    for (int m = 0; m < 2; m++) {
        int r = lane + 32 * m;
#pragma unroll
        for (int n = 0; n < 10; n++) {
            float2 v = up2(acc[m][n]);
            sm[r * OSTR + wrp * 20 + 2 * n]     = v.x;
            sm[r * OSTR + wrp * 20 + 2 * n + 1] = v.y;
        }
    }
    __syncthreads();
    {
        float* dst = g_scratch + split * (BATCH * NC) + mtile * (BM * NC);
        for (int i = t; i < BM * NC; i += 160) {
            int row = i / NC;
            int c   = i - row * NC;
            dst[i] = sm[row * OSTR + c];
        }
    }

    // ---- deterministic cross-CTA reduction (all 512 CTAs resident) ----
    __threadfence();
    __syncthreads();
    if (t == 0) {
        atomicAdd(&g_cnt[mtile], 1u);
        while (atomicAdd(&g_cnt[mtile], 0u) < (unsigned)NSPLIT)
            __nanosleep(64);
    }
    __syncthreads();
    __threadfence();

    // each (mtile,split) CTA reduces exactly 100 outputs of its mtile,
    // summing splits in fixed order 0..63 (bitwise deterministic).
    if (t < 100) {
        const int fo = mtile * (BM * NC) + split * 100 + t;
        float a0 = 0.f, a1 = 0.f, a2 = 0.f, a3 = 0.f;
#pragma unroll
        for (int s = 0; s < NSPLIT; s += 8) {
            float v[8];
#pragma unroll
            for (int u = 0; u < 8; u++)
                v[u] = __ldcg(&g_scratch[(s + u) * (BATCH * NC) + fo]);
            a0 += v[0] + v[4];
            a1 += v[1] + v[5];
            a2 += v[2] + v[6];
            a3 += v[3] + v[7];
        }
        int c = fo % NC;
        out[fo] = (a0 + a1) + (a2 + a3) + g_part1 * g_fcrow[c] + fc_b[c];
    }
}

// ============================================================
extern "C" void kernel_launch(void* const* d_in, const int* in_sizes, int n_in,
                              void* d_out, int out_size) {
    const float* x       = (const float*)d_in[0];   // [512,3072]
    const float* a       = (const float*)d_in[1];   // [3072,3072,1]
    const float* b       = (const float*)d_in[2];   // [3072,3072,1]
    const float* w       = (const float*)d_in[3];   // [5]
    const float* n_param = (const float*)d_in[4];   // [5]
    const float* fc_w    = (const float*)d_in[5];   // [100,3072]
    const float* fc_b    = (const float*)d_in[6];   // [100]
    float* out = (float*)d_out;                     // [512,100]

    k1_prep<<<dim3(3, RS, 3), 256>>>((const float4*)a, (const float4*)b,
                                     fc_w, w, n_param);
    k3_fused<<<dim3(MT, NSPLIT), 160>>>(x, fc_w, fc_b, out);
}

// round 11
// speedup vs baseline: 1.0025x; 1.0008x over previous
#include <cuda_runtime.h>

#define D      3072
#define BATCH  512
#define NC     100
#define RS     48      // row splits for column-sum kernel
#define RROWS  64      // rows per split (48*64 = 3072)
#define BK     48      // GEMM k-tile per CTA (single smem stage)
#define NSPLIT 64      // D / BK
#define BM     64      // GEMM m-tile
#define MT     8       // BATCH / BM
#define ZSTR   49      // Zs row stride (>= BK=48; 49 mod 32 = 17 odd -> conflict-free)
#define WTS    104     // Wt row stride (floats), 16B-aligned rows
#define OSTR   101     // epilogue staging stride

// ---- device scratch (static, no allocation) ----
__device__ float g_pA[RS * D];
__device__ float g_pB[RS * D];
__device__ float g_fcrow[NC];
__device__ float g_part1;
__device__ float g_scratch[NSPLIT * BATCH * NC];   // 13.1 MB
__device__ unsigned g_cnt[MT];

// ---- f32x2 packed-FMA helpers (sm_103a FFMA2) ----
__device__ __forceinline__ unsigned long long pk2(float lo, float hi) {
    unsigned long long r;
    asm("mov.b64 %0, {%1, %2};" : "=l"(r) : "f"(lo), "f"(hi));
    return r;
}
__device__ __forceinline__ void fma2(unsigned long long& d,
                                     unsigned long long a,
                                     unsigned long long b) {
    asm("fma.rn.f32x2 %0, %1, %2, %0;" : "+l"(d) : "l"(a), "l"(b));
}
__device__ __forceinline__ float2 up2(unsigned long long v) {
    float2 f;
    asm("mov.b64 {%0, %1}, %2;" : "=f"(f.x), "=f"(f.y) : "l"(v));
    return f;
}

// ---- FMA-pipe sincos (validated rel_err ~4.5e-7) ----
__device__ __forceinline__ void fast_sincos(float x, float& sn, float& cs) {
    const float BIGMAGIC = 12582912.0f;               // 1.5 * 2^23
    float y = fmaf(x, 0.63661977236758134f, BIGMAGIC);
    unsigned q = __float_as_uint(y);
    float n = y - BIGMAGIC;
    float r = fmaf(n, -1.57079637050628662109375f, x);
    r = fmaf(n, 4.37113900018624283e-8f, r);
    float r2 = r * r;
    float ps = fmaf(r2, -1.9515295891e-4f, 8.3321608736e-3f);
    ps = fmaf(r2, ps, -1.6666654611e-1f);
    float sinp = fmaf(r * r2, ps, r);
    float pc = fmaf(r2, 2.443315711809948e-5f, -1.388731625493765e-3f);
    pc = fmaf(r2, pc, 4.166664568298827e-2f);
    pc = fmaf(r2, pc, -0.5f);
    float cosp = fmaf(r2, pc, 1.0f);
    bool swap = (q & 1u);
    float us = swap ? cosp : sinp;
    float uc = swap ? sinp : cosp;
    sn = __uint_as_float(__float_as_uint(us) ^ ((q & 2u) << 30));
    cs = __uint_as_float(__float_as_uint(uc) ^ (((q + 1u) & 2u) << 30));
}

// ============================================================
// K1: z in {0,1}: partial column sums of a/b (HBM-bound, float4).
//     z == 2   : fcrow row-sums + part1 + counter reset (overlapped).
// grid (3, 48, 3), block 256.
// ============================================================
__global__ void k1_prep(const float4* __restrict__ a,
                        const float4* __restrict__ b,
                        const float* __restrict__ fc_w,
                        const float* __restrict__ w,
                        const float* __restrict__ n_param) {
    if (blockIdx.z < 2) {
        int d4 = blockIdx.x * 256 + threadIdx.x;       // 0..767
        int rs = blockIdx.y;
        const float4* src = (blockIdx.z == 0) ? a : b;
        float*        dst = (blockIdx.z == 0) ? g_pA : g_pB;
        const float4* p = src + rs * RROWS * (D / 4) + d4;
        float4 acc = make_float4(0.f, 0.f, 0.f, 0.f);
#pragma unroll 8
        for (int r = 0; r < RROWS; r++) {
            float4 v = p[r * (D / 4)];
            acc.x += v.x; acc.y += v.y; acc.z += v.z; acc.w += v.w;
        }
        *reinterpret_cast<float4*>(dst + rs * D + d4 * 4) = acc;
        return;
    }
    int flat = blockIdx.y * 3 + blockIdx.x;            // 0..143
    int t = threadIdx.x, wid = t >> 5, lane = t & 31;
    if (flat < 13) {                                   // fcrow: 13 blocks x 8 warps
        int c = flat * 8 + wid;
        if (c < NC) {
            float s = 0.f;
            for (int j = lane; j < D; j += 32) s += fc_w[c * D + j];
#pragma unroll
            for (int o = 16; o; o >>= 1) s += __shfl_xor_sync(0xffffffffu, s, o);
            if (lane == 0) g_fcrow[c] = s;
        }
    } else if (flat == 13) {
        if (t == 0) {
            float p1 = 0.f;
#pragma unroll
            for (int i = 0; i < 4; i++)
                p1 += w[i + 1] * n_param[i + 1] + w[i] * n_param[i];
            g_part1 = p1;
        }
        if (t < MT) g_cnt[t] = 0u;                     // reset spin counters
    }
}

// ============================================================
// K3: fused Z-build + FFMA2 GEMM + deterministic cross-CTA reduce.
// grid (8, 64) = 512 CTAs (single wave at occ 4), block 160 (5 warps).
// Warp w covers cols [w*20, w*20+20) as 10 natural (c, c+1) pairs read
// straight from smem via ulonglong2 (LDS.128 broadcast, zero movs).
// Thread tile = 2 rows x 20 cols.
// ============================================================
__global__ __launch_bounds__(160, 4)
void k3_fused(const float* __restrict__ xf, const float* __restrict__ fc_w,
              const float* __restrict__ fc_b, float* __restrict__ out) {
    __shared__ float colAs[BK], colBs[BK];
    __shared__ float sm[BM * ZSTR + BK * WTS];  // 3136 + 4992 = 8128 f = 32.5KB
    float* Zs = sm;                             // [64][49]
    float* Wt = sm + BM * ZSTR;                 // [48][104], cols contiguous

    const int t     = threadIdx.x;
    const int lane  = t & 31;
    const int wrp   = t >> 5;                   // 0..4
    const int mtile = blockIdx.x;               // 0..7
    const int split = blockIdx.y;               // 0..63
    const int k0    = split * BK;

    // ---- prologue: per-CTA colsum finalize for cols [k0, k0+48) ----
    if (t < 96) {
        int c = (t >= 48) ? t - 48 : t;
        const float* src = (t < 48) ? g_pA : g_pB;
        float*       dst = (t < 48) ? colAs : colBs;
        float s = 0.f;
#pragma unroll 8
        for (int r = 0; r < RS; r++) s += src[r * D + k0 + c];
        dst[c] = s;
    }
    __syncthreads();

    // ---- Z tile: 64 rows x 12 quads (poly sincos, FMA pipe) ----
    for (int i = t; i < BM * (BK / 4); i += 160) {
        int row = i / 12;
        int kq  = i - row * 12;
        float4 v = *reinterpret_cast<const float4*>(
            xf + (mtile * BM + row) * D + k0 + kq * 4);
        float vv[4] = {v.x, v.y, v.z, v.w};
#pragma unroll
        for (int j = 0; j < 4; j++) {
            int kk = kq * 4 + j;
            float sn, cs;
            fast_sincos(vv[j], sn, cs);
            Zs[row * ZSTR + kk] = cs * colAs[kk] + sn * colBs[kk];
        }
    }
    // ---- W tile: 100 rows x 12 quads, transposed into Wt[k][c] ----
    for (int i = t; i < NC * (BK / 4); i += 160) {
        int c  = i / 12;
        int kq = i - c * 12;
        float4 v = *reinterpret_cast<const float4*>(fc_w + c * D + k0 + kq * 4);
        Wt[(kq * 4 + 0) * WTS + c] = v.x;
        Wt[(kq * 4 + 1) * WTS + c] = v.y;
        Wt[(kq * 4 + 2) * WTS + c] = v.z;
        Wt[(kq * 4 + 3) * WTS + c] = v.w;
    }
    __syncthreads();

    // ---- mainloop: K=48, 2 rows x 20 cols per thread ----
    unsigned long long acc[2][10];
#pragma unroll
    for (int m = 0; m < 2; m++)
#pragma unroll
        for (int n = 0; n < 10; n++) acc[m][n] = 0ull;

#pragma unroll 3
    for (int k = 0; k < BK; k++) {
        // 5x LDS.128 (warp-uniform broadcast) -> 10 natural (c,c+1) pairs
        const ulonglong2* wp = reinterpret_cast<const ulonglong2*>(
            &Wt[k * WTS + wrp * 20]);
        unsigned long long wv[10];
#pragma unroll
        for (int q = 0; q < 5; q++) {
            ulonglong2 u = wp[q];
            wv[2 * q]     = u.x;      // floats (4q, 4q+1)
            wv[2 * q + 1] = u.y;      // floats (4q+2, 4q+3)
        }
        float z0 = Zs[lane * ZSTR + k];
        float z1 = Zs[(lane + 32) * ZSTR + k];
        unsigned long long zz0 = pk2(z0, z0);
        unsigned long long zz1 = pk2(z1, z1);
#pragma unroll
        for (int n = 0; n < 10; n++) fma2(acc[0][n], zz0, wv[n]);
#pragma unroll
        for (int n = 0; n < 10; n++) fma2(acc[1][n], zz1, wv[n]);
    }
    __syncthreads();

    // ---- epilogue: stage tile -> coalesced scratch stores ----
#pragma unroll
    for (int m = 0; m < 2; m++) {
        int r = lane + 32 * m;
#pragma unroll
        for (int n = 0; n < 10; n++) {
            float2 v = up2(acc[m][n]);
            sm[r * OSTR + wrp * 20 + 2 * n]     = v.x;
            sm[r * OSTR + wrp * 20 + 2 * n + 1] = v.y;
        }
    }
    __syncthreads();
    {
        float* dst = g_scratch + split * (BATCH * NC) + mtile * (BM * NC);
        for (int i = t; i < BM * NC; i += 160) {
            int row = i / NC;
            int c   = i - row * NC;
            dst[i] = sm[row * OSTR + c];
        }
    }

    // ---- deterministic cross-CTA reduction (all 512 CTAs resident) ----
    __threadfence();
    __syncthreads();
    if (t == 0) {
        atomicAdd(&g_cnt[mtile], 1u);
        while (atomicAdd(&g_cnt[mtile], 0u) < (unsigned)NSPLIT)
            __nanosleep(64);
    }
    __syncthreads();
    __threadfence();

    // each (mtile,split) CTA reduces exactly 100 outputs of its mtile,
    // summing splits in fixed order 0..63 (bitwise deterministic).
    if (t < 100) {
        const int fo = mtile * (BM * NC) + split * 100 + t;
        float a0 = 0.f, a1 = 0.f, a2 = 0.f, a3 = 0.f;
#pragma unroll
        for (int s = 0; s < NSPLIT; s += 8) {
            float v[8];
#pragma unroll
            for (int u = 0; u < 8; u++)
                v[u] = __ldcg(&g_scratch[(s + u) * (BATCH * NC) + fo]);
            a0 += v[0] + v[4];
            a1 += v[1] + v[5];
            a2 += v[2] + v[6];
            a3 += v[3] + v[7];
        }
        int c = fo % NC;
        out[fo] = (a0 + a1) + (a2 + a3) + g_part1 * g_fcrow[c] + fc_b[c];
    }
}

// ============================================================
extern "C" void kernel_launch(void* const* d_in, const int* in_sizes, int n_in,
                              void* d_out, int out_size) {
    const float* x       = (const float*)d_in[0];   // [512,3072]
    const float* a       = (const float*)d_in[1];   // [3072,3072,1]
    const float* b       = (const float*)d_in[2];   // [3072,3072,1]
    const float* w       = (const float*)d_in[3];   // [5]
    const float* n_param = (const float*)d_in[4];   // [5]
    const float* fc_w    = (const float*)d_in[5];   // [100,3072]
    const float* fc_b    = (const float*)d_in[6];   // [100]
    float* out = (float*)d_out;                     // [512,100]

    k1_prep<<<dim3(3, RS, 3), 256>>>((const float4*)a, (const float4*)b,
                                     fc_w, w, n_param);
    k3_fused<<<dim3(MT, NSPLIT), 160>>>(x, fc_w, fc_b, out);
}

// round 12
// speedup vs baseline: 1.0374x; 1.0349x over previous
#include <cuda_runtime.h>

#define D      3072
#define BATCH  512
#define NC     100
#define RS     48      // row splits for column-sum kernel
#define RROWS  64      // rows per split (48*64 = 3072)
#define BK     64      // GEMM k-tile per CTA (single smem stage)
#define NSPLIT 48      // D / BK
#define BM     64      // GEMM m-tile
#define MT     8       // BATCH / BM
#define ZSTR   65      // Zs row stride (>= BK; 65 mod 32 = 1 -> conflict-free)
#define WTS    104     // Wt row stride (floats), 16B-aligned rows
#define OSTR   101     // epilogue staging stride

// ---- device scratch (static, no allocation) ----
__device__ float g_pA[RS * D];
__device__ float g_pB[RS * D];
__device__ float g_fcrow[NC];
__device__ float g_part1;
__device__ float g_scratch[NSPLIT * BATCH * NC];   // 9.8 MB
__device__ unsigned g_cnt[MT];

// ---- f32x2 packed-FMA helpers (sm_103a FFMA2, rt2 confirmed by profile) ----
__device__ __forceinline__ unsigned long long pk2(float lo, float hi) {
    unsigned long long r;
    asm("mov.b64 %0, {%1, %2};" : "=l"(r) : "f"(lo), "f"(hi));
    return r;
}
__device__ __forceinline__ void fma2(unsigned long long& d,
                                     unsigned long long a,
                                     unsigned long long b) {
    asm("fma.rn.f32x2 %0, %1, %2, %0;" : "+l"(d) : "l"(a), "l"(b));
}
__device__ __forceinline__ float2 up2(unsigned long long v) {
    float2 f;
    asm("mov.b64 {%0, %1}, %2;" : "=f"(f.x), "=f"(f.y) : "l"(v));
    return f;
}

// ---- FMA-pipe sincos (validated rel_err ~4.5e-7) ----
__device__ __forceinline__ void fast_sincos(float x, float& sn, float& cs) {
    const float BIGMAGIC = 12582912.0f;               // 1.5 * 2^23
    float y = fmaf(x, 0.63661977236758134f, BIGMAGIC);
    unsigned q = __float_as_uint(y);
    float n = y - BIGMAGIC;
    float r = fmaf(n, -1.57079637050628662109375f, x);
    r = fmaf(n, 4.37113900018624283e-8f, r);
    float r2 = r * r;
    float ps = fmaf(r2, -1.9515295891e-4f, 8.3321608736e-3f);
    ps = fmaf(r2, ps, -1.6666654611e-1f);
    float sinp = fmaf(r * r2, ps, r);
    float pc = fmaf(r2, 2.443315711809948e-5f, -1.388731625493765e-3f);
    pc = fmaf(r2, pc, 4.166664568298827e-2f);
    pc = fmaf(r2, pc, -0.5f);
    float cosp = fmaf(r2, pc, 1.0f);
    bool swap = (q & 1u);
    float us = swap ? cosp : sinp;
    float uc = swap ? sinp : cosp;
    sn = __uint_as_float(__float_as_uint(us) ^ ((q & 2u) << 30));
    cs = __uint_as_float(__float_as_uint(uc) ^ (((q + 1u) & 2u) << 30));
}

// ============================================================
// K1: z in {0,1}: partial column sums of a/b (HBM-bound, float4).
//     z == 2   : fcrow row-sums + part1 + counter reset (overlapped).
// grid (3, 48, 3), block 256.
// ============================================================
__global__ void k1_prep(const float4* __restrict__ a,
                        const float4* __restrict__ b,
                        const float* __restrict__ fc_w,
                        const float* __restrict__ w,
                        const float* __restrict__ n_param) {
    if (blockIdx.z < 2) {
        int d4 = blockIdx.x * 256 + threadIdx.x;       // 0..767
        int rs = blockIdx.y;
        const float4* src = (blockIdx.z == 0) ? a : b;
        float*        dst = (blockIdx.z == 0) ? g_pA : g_pB;
        const float4* p = src + rs * RROWS * (D / 4) + d4;
        float4 acc = make_float4(0.f, 0.f, 0.f, 0.f);
#pragma unroll 8
        for (int r = 0; r < RROWS; r++) {
            float4 v = p[r * (D / 4)];
            acc.x += v.x; acc.y += v.y; acc.z += v.z; acc.w += v.w;
        }
        *reinterpret_cast<float4*>(dst + rs * D + d4 * 4) = acc;
        return;
    }
    int flat = blockIdx.y * 3 + blockIdx.x;            // 0..143
    int t = threadIdx.x, wid = t >> 5, lane = t & 31;
    if (flat < 13) {                                   // fcrow: 13 blocks x 8 warps
        int c = flat * 8 + wid;
        if (c < NC) {
            float s = 0.f;
            for (int j = lane; j < D; j += 32) s += fc_w[c * D + j];
#pragma unroll
            for (int o = 16; o; o >>= 1) s += __shfl_xor_sync(0xffffffffu, s, o);
            if (lane == 0) g_fcrow[c] = s;
        }
    } else if (flat == 13) {
        if (t == 0) {
            float p1 = 0.f;
#pragma unroll
            for (int i = 0; i < 4; i++)
                p1 += w[i + 1] * n_param[i + 1] + w[i] * n_param[i];
            g_part1 = p1;
        }
        if (t < MT) g_cnt[t] = 0u;                     // reset spin counters
    }
}

// ============================================================
// K3: fused Z-build + FFMA2 GEMM + deterministic cross-CTA reduce.
// grid (8, 48) = 384 CTAs; block 320 (10 warps); occ 3 -> 30 warps/SM,
// 384 <= 444 resident capacity so the spin barrier is deadlock-free.
// Warp cg covers cols [cg*10, cg*10+10) as 5 natural LDS.64 pairs
// (warp-uniform broadcast). Thread tile = 2 rows (lane, lane+32) x 10 cols.
// acc = 10 u64 (20 regs) -> fits 68-reg cap at occ 3 without spill.
// ============================================================
__global__ __launch_bounds__(320, 3)
void k3_fused(const float* __restrict__ xf, const float* __restrict__ fc_w,
              const float* __restrict__ fc_b, float* __restrict__ out) {
    __shared__ float colAs[BK], colBs[BK];
    __shared__ float sm[BM * ZSTR + BK * WTS];  // 4160 + 6656 = 10816 f = 43.3KB
    float* Zs = sm;                             // [64][65]
    float* Wt = sm + BM * ZSTR;                 // [64][104], cols contiguous

    const int t     = threadIdx.x;
    const int lane  = t & 31;
    const int cg    = t >> 5;                   // warp id 0..9 -> col group
    const int mtile = blockIdx.x;               // 0..7
    const int split = blockIdx.y;               // 0..47
    const int k0    = split * BK;

    // ---- prologue: per-CTA colsum finalize for cols [k0, k0+64) ----
    if (t < 128) {
        int c = t & 63;
        const float* src = (t < 64) ? g_pA : g_pB;
        float*       dst = (t < 64) ? colAs : colBs;
        float s = 0.f;
#pragma unroll 8
        for (int r = 0; r < RS; r++) s += src[r * D + k0 + c];
        dst[c] = s;
    }
    __syncthreads();

    // ---- Z tile: 64 rows x 16 quads (poly sincos, FMA pipe) ----
    for (int i = t; i < BM * (BK / 4); i += 320) {
        int row = i >> 4;
        int kq  = i & 15;
        float4 v = *reinterpret_cast<const float4*>(
            xf + (mtile * BM + row) * D + k0 + kq * 4);
        float vv[4] = {v.x, v.y, v.z, v.w};
#pragma unroll
        for (int j = 0; j < 4; j++) {
            int kk = kq * 4 + j;
            float sn, cs;
            fast_sincos(vv[j], sn, cs);
            Zs[row * ZSTR + kk] = cs * colAs[kk] + sn * colBs[kk];
        }
    }
    // ---- W tile: 100 rows x 16 quads, transposed into Wt[k][c] ----
    for (int i = t; i < NC * (BK / 4); i += 320) {
        int c  = i >> 4;
        int kq = i & 15;
        float4 v = *reinterpret_cast<const float4*>(fc_w + c * D + k0 + kq * 4);
        Wt[(kq * 4 + 0) * WTS + c] = v.x;
        Wt[(kq * 4 + 1) * WTS + c] = v.y;
        Wt[(kq * 4 + 2) * WTS + c] = v.z;
        Wt[(kq * 4 + 3) * WTS + c] = v.w;
    }
    __syncthreads();

    // ---- mainloop: K=64, 2 rows x 10 cols per thread ----
    unsigned long long acc[2][5];
#pragma unroll
    for (int m = 0; m < 2; m++)
#pragma unroll
        for (int n = 0; n < 5; n++) acc[m][n] = 0ull;

#pragma unroll 4
    for (int k = 0; k < BK; k++) {
        // 5x LDS.64 (warp-uniform broadcast), natural (c, c+1) pairs
        const unsigned long long* wp =
            reinterpret_cast<const unsigned long long*>(&Wt[k * WTS + cg * 10]);
        unsigned long long wv[5];
#pragma unroll
        for (int q = 0; q < 5; q++) wv[q] = wp[q];
        float z0 = Zs[lane * ZSTR + k];
        float z1 = Zs[(lane + 32) * ZSTR + k];
        unsigned long long zz0 = pk2(z0, z0);
        unsigned long long zz1 = pk2(z1, z1);
#pragma unroll
        for (int n = 0; n < 5; n++) fma2(acc[0][n], zz0, wv[n]);
#pragma unroll
        for (int n = 0; n < 5; n++) fma2(acc[1][n], zz1, wv[n]);
    }
    __syncthreads();

    // ---- epilogue: stage tile -> coalesced scratch stores ----
#pragma unroll
    for (int m = 0; m < 2; m++) {
        int r = lane + 32 * m;
#pragma unroll
        for (int n = 0; n < 5; n++) {
            float2 v = up2(acc[m][n]);
            sm[r * OSTR + cg * 10 + 2 * n]     = v.x;
            sm[r * OSTR + cg * 10 + 2 * n + 1] = v.y;
        }
    }
    __syncthreads();
    {
        float* dst = g_scratch + split * (BATCH * NC) + mtile * (BM * NC);
        for (int i = t; i < BM * NC; i += 320) {
            int row = i / NC;
            int c   = i - row * NC;
            dst[i] = sm[row * OSTR + c];
        }
    }

    // ---- deterministic cross-CTA reduction (all 384 CTAs resident) ----
    __threadfence();
    __syncthreads();
    if (t == 0) {
        atomicAdd(&g_cnt[mtile], 1u);
        while (atomicAdd(&g_cnt[mtile], 0u) < (unsigned)NSPLIT)
            __nanosleep(64);
    }
    __syncthreads();
    __threadfence();

    // splits 0..31 reduce 200 outputs each (mtile covers 6400 outputs),
    // summing splits in fixed order 0..47 (bitwise deterministic).
    if (split < 32 && t < 200) {
        const int fo = mtile * (BM * NC) + split * 200 + t;
        float a0 = 0.f, a1 = 0.f, a2 = 0.f, a3 = 0.f;
#pragma unroll
        for (int s = 0; s < NSPLIT; s += 8) {
            float v[8];
#pragma unroll
            for (int u = 0; u < 8; u++)
                v[u] = __ldcg(&g_scratch[(s + u) * (BATCH * NC) + fo]);
            a0 += v[0] + v[4];
            a1 += v[1] + v[5];
            a2 += v[2] + v[6];
            a3 += v[3] + v[7];
        }
        int c = fo % NC;
        out[fo] = (a0 + a1) + (a2 + a3) + g_part1 * g_fcrow[c] + fc_b[c];
    }
}

// ============================================================
extern "C" void kernel_launch(void* const* d_in, const int* in_sizes, int n_in,
                              void* d_out, int out_size) {
    const float* x       = (const float*)d_in[0];   // [512,3072]
    const float* a       = (const float*)d_in[1];   // [3072,3072,1]
    const float* b       = (const float*)d_in[2];   // [3072,3072,1]
    const float* w       = (const float*)d_in[3];   // [5]
    const float* n_param = (const float*)d_in[4];   // [5]
    const float* fc_w    = (const float*)d_in[5];   // [100,3072]
    const float* fc_b    = (const float*)d_in[6];   // [100]
    float* out = (float*)d_out;                     // [512,100]

    k1_prep<<<dim3(3, RS, 3), 256>>>((const float4*)a, (const float4*)b,
                                     fc_w, w, n_param);
    k3_fused<<<dim3(MT, NSPLIT), 320>>>(x, fc_w, fc_b, out);
}

// round 13
// speedup vs baseline: 1.0445x; 1.0068x over previous
#include <cuda_runtime.h>

#define D      3072
#define BATCH  512
#define NC     100
#define RS     48      // row splits for column-sum kernel
#define RROWS  64      // rows per split (48*64 = 3072)
#define BK     64      // GEMM k-tile per CTA (single smem stage)
#define NSPLIT 48      // D / BK
#define BM     64      // GEMM m-tile
#define MT     8       // BATCH / BM
#define ZSTR   65      // Zs row stride (>= BK; 65 mod 32 = 1 -> conflict-free)
#define WTS    104     // Wt row stride (floats), 16B-aligned rows
#define OSTR   101     // epilogue staging stride

// ---- device scratch (static, no allocation) ----
__device__ float g_pA[RS * D];
__device__ float g_pB[RS * D];
__device__ float g_fcrow[NC];
__device__ float g_part1;
__device__ float g_scratch[NSPLIT * BATCH * NC];   // 9.8 MB
__device__ unsigned g_cnt[MT];

// ---- f32x2 packed-FMA helpers (sm_103a FFMA2, rt2 confirmed by profile) ----
__device__ __forceinline__ unsigned long long pk2(float lo, float hi) {
    unsigned long long r;
    asm("mov.b64 %0, {%1, %2};" : "=l"(r) : "f"(lo), "f"(hi));
    return r;
}
__device__ __forceinline__ void fma2(unsigned long long& d,
                                     unsigned long long a,
                                     unsigned long long b) {
    asm("fma.rn.f32x2 %0, %1, %2, %0;" : "+l"(d) : "l"(a), "l"(b));
}
__device__ __forceinline__ float2 up2(unsigned long long v) {
    float2 f;
    asm("mov.b64 {%0, %1}, %2;" : "=f"(f.x), "=f"(f.y) : "l"(v));
    return f;
}

// ---- FMA-pipe sincos (validated rel_err ~4.5e-7) ----
__device__ __forceinline__ void fast_sincos(float x, float& sn, float& cs) {
    const float BIGMAGIC = 12582912.0f;               // 1.5 * 2^23
    float y = fmaf(x, 0.63661977236758134f, BIGMAGIC);
    unsigned q = __float_as_uint(y);
    float n = y - BIGMAGIC;
    float r = fmaf(n, -1.57079637050628662109375f, x);
    r = fmaf(n, 4.37113900018624283e-8f, r);
    float r2 = r * r;
    float ps = fmaf(r2, -1.9515295891e-4f, 8.3321608736e-3f);
    ps = fmaf(r2, ps, -1.6666654611e-1f);
    float sinp = fmaf(r * r2, ps, r);
    float pc = fmaf(r2, 2.443315711809948e-5f, -1.388731625493765e-3f);
    pc = fmaf(r2, pc, 4.166664568298827e-2f);
    pc = fmaf(r2, pc, -0.5f);
    float cosp = fmaf(r2, pc, 1.0f);
    bool swap = (q & 1u);
    float us = swap ? cosp : sinp;
    float uc = swap ? sinp : cosp;
    sn = __uint_as_float(__float_as_uint(us) ^ ((q & 2u) << 30));
    cs = __uint_as_float(__float_as_uint(uc) ^ (((q + 1u) & 2u) << 30));
}

// ============================================================
// K1: z in {0,1}: partial column sums of a/b (HBM-bound, float4).
//     z == 2   : fcrow row-sums + part1 + counter reset (overlapped).
// grid (3, 48, 3), block 256.
// ============================================================
__global__ void k1_prep(const float4* __restrict__ a,
                        const float4* __restrict__ b,
                        const float* __restrict__ fc_w,
                        const float* __restrict__ w,
                        const float* __restrict__ n_param) {
    if (blockIdx.z < 2) {
        int d4 = blockIdx.x * 256 + threadIdx.x;       // 0..767
        int rs = blockIdx.y;
        const float4* src = (blockIdx.z == 0) ? a : b;
        float*        dst = (blockIdx.z == 0) ? g_pA : g_pB;
        const float4* p = src + rs * RROWS * (D / 4) + d4;
        float4 acc = make_float4(0.f, 0.f, 0.f, 0.f);
#pragma unroll 8
        for (int r = 0; r < RROWS; r++) {
            float4 v = p[r * (D / 4)];
            acc.x += v.x; acc.y += v.y; acc.z += v.z; acc.w += v.w;
        }
        *reinterpret_cast<float4*>(dst + rs * D + d4 * 4) = acc;
        return;
    }
    int flat = blockIdx.y * 3 + blockIdx.x;            // 0..143
    int t = threadIdx.x, wid = t >> 5, lane = t & 31;
    if (flat < 13) {                                   // fcrow: 13 blocks x 8 warps
        int c = flat * 8 + wid;
        if (c < NC) {
            float s = 0.f;
            for (int j = lane; j < D; j += 32) s += fc_w[c * D + j];
#pragma unroll
            for (int o = 16; o; o >>= 1) s += __shfl_xor_sync(0xffffffffu, s, o);
            if (lane == 0) g_fcrow[c] = s;
        }
    } else if (flat == 13) {
        if (t == 0) {
            float p1 = 0.f;
#pragma unroll
            for (int i = 0; i < 4; i++)
                p1 += w[i + 1] * n_param[i + 1] + w[i] * n_param[i];
            g_part1 = p1;
        }
        if (t < MT) g_cnt[t] = 0u;                     // reset spin counters
    }
}

// ============================================================
// K3: fused Z-build + FFMA2 GEMM + deterministic cross-CTA reduce.
// grid (8, 48) = 384 CTAs; block 320 (10 warps); occ 3 -> 30 warps/SM,
// 384 <= 444 resident capacity so the spin barrier is deadlock-free.
// Warp cg covers cols [cg*10, cg*10+10) as 5 natural LDS.64 pairs
// (warp-uniform broadcast). Thread tile = 2 rows (lane, lane+32) x 10 cols.
// acc = 10 u64 (20 regs) -> fits 68-reg cap at occ 3 without spill.
// ============================================================
__global__ __launch_bounds__(320, 3)
void k3_fused(const float* __restrict__ xf, const float* __restrict__ fc_w,
              const float* __restrict__ fc_b, float* __restrict__ out) {
    __shared__ float colAs[BK], colBs[BK];
    __shared__ float sm[BM * ZSTR + BK * WTS];  // 4160 + 6656 = 10816 f = 43.3KB
    float* Zs = sm;                             // [64][65]
    float* Wt = sm + BM * ZSTR;                 // [64][104], cols contiguous

    const int t     = threadIdx.x;
    const int lane  = t & 31;
    const int cg    = t >> 5;                   // warp id 0..9 -> col group
    const int mtile = blockIdx.x;               // 0..7
    const int split = blockIdx.y;               // 0..47
    const int k0    = split * BK;

    // ---- prologue: per-CTA colsum finalize for cols [k0, k0+64) ----
    if (t < 128) {
        int c = t & 63;
        const float* src = (t < 64) ? g_pA : g_pB;
        float*       dst = (t < 64) ? colAs : colBs;
        float s = 0.f;
#pragma unroll 8
        for (int r = 0; r < RS; r++) s += src[r * D + k0 + c];
        dst[c] = s;
    }
    __syncthreads();

    // ---- Z tile: 64 rows x 16 quads (poly sincos, FMA pipe) ----
    for (int i = t; i < BM * (BK / 4); i += 320) {
        int row = i >> 4;
        int kq  = i & 15;
        float4 v = *reinterpret_cast<const float4*>(
            xf + (mtile * BM + row) * D + k0 + kq * 4);
        float vv[4] = {v.x, v.y, v.z, v.w};
#pragma unroll
        for (int j = 0; j < 4; j++) {
            int kk = kq * 4 + j;
            float sn, cs;
            fast_sincos(vv[j], sn, cs);
            Zs[row * ZSTR + kk] = cs * colAs[kk] + sn * colBs[kk];
        }
    }
    // ---- W tile: 100 rows x 16 quads, transposed into Wt[k][c] ----
    for (int i = t; i < NC * (BK / 4); i += 320) {
        int c  = i >> 4;
        int kq = i & 15;
        float4 v = *reinterpret_cast<const float4*>(fc_w + c * D + k0 + kq * 4);
        Wt[(kq * 4 + 0) * WTS + c] = v.x;
        Wt[(kq * 4 + 1) * WTS + c] = v.y;
        Wt[(kq * 4 + 2) * WTS + c] = v.z;
        Wt[(kq * 4 + 3) * WTS + c] = v.w;
    }
    __syncthreads();

    // ---- mainloop: K=64, 2 rows x 10 cols per thread ----
    unsigned long long acc[2][5];
#pragma unroll
    for (int m = 0; m < 2; m++)
#pragma unroll
        for (int n = 0; n < 5; n++) acc[m][n] = 0ull;

#pragma unroll 4
    for (int k = 0; k < BK; k++) {
        // 5x LDS.64 (warp-uniform broadcast), natural (c, c+1) pairs
        const unsigned long long* wp =
            reinterpret_cast<const unsigned long long*>(&Wt[k * WTS + cg * 10]);
        unsigned long long wv[5];
#pragma unroll
        for (int q = 0; q < 5; q++) wv[q] = wp[q];
        float z0 = Zs[lane * ZSTR + k];
        float z1 = Zs[(lane + 32) * ZSTR + k];
        unsigned long long zz0 = pk2(z0, z0);
        unsigned long long zz1 = pk2(z1, z1);
#pragma unroll
        for (int n = 0; n < 5; n++) fma2(acc[0][n], zz0, wv[n]);
#pragma unroll
        for (int n = 0; n < 5; n++) fma2(acc[1][n], zz1, wv[n]);
    }
    __syncthreads();

    // ---- epilogue: stage tile -> coalesced scratch stores ----
#pragma unroll
    for (int m = 0; m < 2; m++) {
        int r = lane + 32 * m;
#pragma unroll
        for (int n = 0; n < 5; n++) {
            float2 v = up2(acc[m][n]);
            sm[r * OSTR + cg * 10 + 2 * n]     = v.x;
            sm[r * OSTR + cg * 10 + 2 * n + 1] = v.y;
        }
    }
    __syncthreads();
    {
        float* dst = g_scratch + split * (BATCH * NC) + mtile * (BM * NC);
        for (int i = t; i < BM * NC; i += 320) {
            int row = i / NC;
            int c   = i - row * NC;
            dst[i] = sm[row * OSTR + c];
        }
    }

    // ---- deterministic cross-CTA reduction (all 384 CTAs resident) ----
    __threadfence();
    __syncthreads();
    if (t == 0) {
        atomicAdd(&g_cnt[mtile], 1u);
        while (atomicAdd(&g_cnt[mtile], 0u) < (unsigned)NSPLIT)
            __nanosleep(64);
    }
    __syncthreads();
    __threadfence();

    // splits 0..31 reduce 200 outputs each (mtile covers 6400 outputs),
    // summing splits in fixed order 0..47 (bitwise deterministic).
    if (split < 32 && t < 200) {
        const int fo = mtile * (BM * NC) + split * 200 + t;
        float a0 = 0.f, a1 = 0.f, a2 = 0.f, a3 = 0.f;
#pragma unroll
        for (int s = 0; s < NSPLIT; s += 8) {
            float v[8];
#pragma unroll
            for (int u = 0; u < 8; u++)
                v[u] = __ldcg(&g_scratch[(s + u) * (BATCH * NC) + fo]);
            a0 += v[0] + v[4];
            a1 += v[1] + v[5];
            a2 += v[2] + v[6];
            a3 += v[3] + v[7];
        }
        int c = fo % NC;
        out[fo] = (a0 + a1) + (a2 + a3) + g_part1 * g_fcrow[c] + fc_b[c];
    }
}

// ============================================================
extern "C" void kernel_launch(void* const* d_in, const int* in_sizes, int n_in,
                              void* d_out, int out_size) {
    const float* x       = (const float*)d_in[0];   // [512,3072]
    const float* a       = (const float*)d_in[1];   // [3072,3072,1]
    const float* b       = (const float*)d_in[2];   // [3072,3072,1]
    const float* w       = (const float*)d_in[3];   // [5]
    const float* n_param = (const float*)d_in[4];   // [5]
    const float* fc_w    = (const float*)d_in[5];   // [100,3072]
    const float* fc_b    = (const float*)d_in[6];   // [100]
    float* out = (float*)d_out;                     // [512,100]

    k1_prep<<<dim3(3, RS, 3), 256>>>((const float4*)a, (const float4*)b,
                                     fc_w, w, n_param);
    k3_fused<<<dim3(MT, NSPLIT), 320>>>(x, fc_w, fc_b, out);
}